// round 14
// baseline (speedup 1.0000x reference)
#include <cuda_runtime.h>
#include <cuda_fp16.h>
#include <cstdint>
#include <math.h>

#define HH 1024      // detector size / image size
#define AA 180       // number of angles
#define BB 16        // batch
#define NBQ (BB / 4) // batch quads
#define NBO (BB / 8) // batch octets

#define ROWP 1028    // uint4 entries per padded row (valid j 0..1025)
#define MTAP 64      // filter taps: m < MTAP, i.e. |d| <= 127 (tail ~1.3e-4 rel)

// V-only fp16 window entries, one uint4 per detector position j per octet:
//   entry[j] = half x8 = ( v_b0[j-1], v_b1[j-1], ..., v_b7[j-1] )
// with v[-1] = v[1024] = 0. Bilinear pair (v[j0], v[j0+1]) = entries j0+1, j0+2.
__device__ uint4 g_wv[NBO * AA * ROWP];
// Transposed raw sinogram: g_xt[b][a][h] (for coalesced filter input reads)
__device__ float g_xt[BB * AA * HH];
// Pre-scaled trig: g_cs[a] = 512*cos(theta_a), g_ns[a] = -512*sin(theta_a)
__device__ float g_cs[AA];
__device__ float g_ns[AA];

// ---------------------------------------------------------------------------
// cp.async helpers (16-byte, L2-cg path)
// ---------------------------------------------------------------------------
__device__ __forceinline__ void cp_async16(unsigned int dst_smem, const void* src) {
    asm volatile("cp.async.cg.shared.global [%0], [%1], 16;\n"
                 :: "r"(dst_smem), "l"(src));
}
__device__ __forceinline__ void cp_async_commit() {
    asm volatile("cp.async.commit_group;\n");
}
__device__ __forceinline__ void cp_async_wait0() {
    asm volatile("cp.async.wait_group 0;\n" ::: "memory");
}

// ---------------------------------------------------------------------------
// Kernel 0: coalesced transpose x[b][h][a] -> g_xt[b][a][h].
// Block 32x8, 32x32 tile, 4 elements per thread (ILP for latency hiding).
// ---------------------------------------------------------------------------
__global__ __launch_bounds__(256) void transpose_kernel(const float* __restrict__ x) {
    __shared__ float t[32][33];
    const int b  = blockIdx.z;
    const int a0 = blockIdx.x * 32;
    const int h0 = blockIdx.y * 32;

    const int a = a0 + threadIdx.x;
    #pragma unroll
    for (int j = 0; j < 4; j++) {
        int h = h0 + threadIdx.y + 8 * j;
        t[threadIdx.y + 8 * j][threadIdx.x] =
            (a < AA) ? x[((size_t)b * HH + h) * AA + a] : 0.0f;
    }
    __syncthreads();

    const int ho = h0 + threadIdx.x;
    #pragma unroll
    for (int j = 0; j < 4; j++) {
        int ao = a0 + threadIdx.y + 8 * j;
        if (ao < AA)
            g_xt[((size_t)b * AA + ao) * HH + ho] = t[threadIdx.x][threadIdx.y + 8 * j];
    }
}

// ---------------------------------------------------------------------------
// Kernel 1: angle-resample + truncated ramp-filter convolution (equivalent to
// the reference's wrap-free padded-FFT filtering; taps beyond |d|=127 dropped,
// tail ~1.3e-4 relative, under the fp16 window quantization).
// 4 batches (one quad) per block; each quad writes its 8-byte half of the
// octet's uint4 entries with coalesced uint2 stores.
// One block per (angle, quad). 256 threads, 4 outputs per thread per batch.
// ---------------------------------------------------------------------------
#define FPAD 128                 // conv pad each side (>= MTAP*2-1)
#define FROW (FPAD + HH + FPAD)  // 1280 floats per padded column

__global__ __launch_bounds__(256) void filter_kernel() {
    const int a   = blockIdx.x;
    const int bq  = blockIdx.y;       // batch quad
    const int tid = threadIdx.x;

    if (bq == 0 && tid == 0) {
        float tf = (float)a * 0.017453292519943295f;   // reference f32 angle
        double t = (double)tf;
        g_cs[a] = (float)cos(t) * 512.0f;
        g_ns[a] = (float)(-sin(t)) * 512.0f;
    }

    __shared__ float sin_[4][FROW];   // padded resampled columns (zeros outside)
    __shared__ float vcol[4][HH];     // filtered columns
    __shared__ float coef[MTAP];      // coef[m] = -2 / (pi*(2m+1))^2

    #pragma unroll
    for (int q = 0; q < 4; q++) {
        for (int i = tid; i < FPAD; i += 256) {
            sin_[q][i] = 0.0f;
            sin_[q][FPAD + HH + i] = 0.0f;
        }
    }
    if (tid < MTAP) {
        float d  = 2.0f * (float)tid + 1.0f;
        float pd = 3.14159265358979323846f * d;
        coef[tid] = -2.0f / (pd * pd);
    }

    // angle interpolation weights (commute with the linear filter)
    float ix = (float)a * (float)(180.0 / 179.0) - 0.5f;
    float fl = floorf(ix);
    int   i0 = (int)fl;
    float fx = ix - fl;
    int   i1 = i0 + 1;
    float w0 = (i0 >= 0 && i0 < AA) ? (1.0f - fx) : 0.0f;
    float w1 = (i1 >= 0 && i1 < AA) ? fx : 0.0f;
    int   c0 = min(max(i0, 0), AA - 1);
    int   c1 = min(max(i1, 0), AA - 1);

    // coalesced loads of the 4 batches' resampled columns
    #pragma unroll
    for (int q = 0; q < 4; q++) {
        int b = 4 * bq + q;
        const float* __restrict__ r0 = g_xt + ((size_t)b * AA + c0) * HH;
        const float* __restrict__ r1 = g_xt + ((size_t)b * AA + c1) * HH;
        for (int k = tid; k < HH; k += 256) {
            sin_[q][FPAD + k] = w0 * r0[k] + w1 * r1[k];
        }
    }
    __syncthreads();

    // truncated ramp convolution, batch by batch (order matches prior rounds)
    #pragma unroll
    for (int q = 0; q < 4; q++) {
        const float* __restrict__ s = sin_[q];
        const int p0 = FPAD + tid;
        float acc0 = 0.5f * s[p0];
        float acc1 = 0.5f * s[p0 + 256];
        float acc2 = 0.5f * s[p0 + 512];
        float acc3 = 0.5f * s[p0 + 768];

        #pragma unroll 8
        for (int m = 0; m < MTAP; m++) {
            int   d = 2 * m + 1;
            float c = coef[m];
            acc0 = fmaf(c, s[p0 - d]       + s[p0 + d],       acc0);
            acc1 = fmaf(c, s[p0 + 256 - d] + s[p0 + 256 + d], acc1);
            acc2 = fmaf(c, s[p0 + 512 - d] + s[p0 + 512 + d], acc2);
            acc3 = fmaf(c, s[p0 + 768 - d] + s[p0 + 768 + d], acc3);
        }
        vcol[q][tid]       = acc0;
        vcol[q][tid + 256] = acc1;
        vcol[q][tid + 512] = acc2;
        vcol[q][tid + 768] = acc3;
    }
    __syncthreads();

    // store this quad's 8-byte half of each uint4 entry (entry[j] = v[j-1])
    char* wrow = (char*)(g_wv + ((size_t)(bq >> 1) * AA + a) * ROWP)
               + (bq & 1) * 8;
    for (int j = tid; j < 1026; j += 256) {
        float vm1[4];
        #pragma unroll
        for (int q = 0; q < 4; q++)
            vm1[q] = (j >= 1 && j <= 1024) ? vcol[q][j - 1] : 0.0f;
        __half2 p01 = __floats2half2_rn(vm1[0], vm1[1]);
        __half2 p23 = __floats2half2_rn(vm1[2], vm1[3]);
        uint2 e;
        e.x = *reinterpret_cast<unsigned int*>(&p01);
        e.y = *reinterpret_cast<unsigned int*>(&p23);
        *reinterpret_cast<uint2*>(wrow + (size_t)j * 16) = e;
    }
}

// ---------------------------------------------------------------------------
// Kernel 2: backprojection, 8 batches per block, v-only fp16 uint4 windows.
// Bilinear sample = entries k and k+1 (two LDS.128 per 8 samples); diff is
// computed in-loop via HSUB2 (staging smem writes halved vs (v,d) layout).
// Block = 32x8 = 256 threads = 32x32 pixel tile, 4 y-rows x 8 batches/thread.
// Double-buffered window staging via cp.async; one barrier per chunk.
// Window bounds from tile-corner extremes -> k in [0, slotWIN+45]; no clamp.
// ---------------------------------------------------------------------------
#define CH  12                 // angles per chunk (180 = 15 * 12)
#define NCH (AA / CH)
#define WIN 48                 // window entries per angle (44 span + guards)
#define CWIN (CH * WIN)        // 576 entries per chunk

__global__ __launch_bounds__(256) void backproject_kernel(float* __restrict__ out) {
    __shared__ float4 s_meta[AA];            // cs, ns, off(=511.5-jminf+slot*WIN), 0
    __shared__ int    s_jmin[AA];
    __shared__ uint4  s_w[2][CWIN];          // [buf][entry]  (18.4 KB)

    const int tid = threadIdx.y * 32 + threadIdx.x;
    const int bo  = blockIdx.z;              // batch octet
    const int x0  = blockIdx.x * 32;
    const int y0  = blockIdx.y * 32;

    const float step = 2.0f / 1023.0f;
    const float ux_lo = fmaf((float)x0,        step, -1.0f);
    const float ux_hi = fmaf((float)(x0 + 31), step, -1.0f);
    const float uy_lo = fmaf((float)y0,        step, -1.0f);
    const float uy_hi = fmaf((float)(y0 + 31), step, -1.0f);

    const int px    = x0 + threadIdx.x;
    const int ybase = y0 + threadIdx.y * 4;
    float* ob = out + (size_t)(8 * bo) * HH * HH;

    const float ux = fmaf((float)px, step, -1.0f);
    float uy[4];
    #pragma unroll
    for (int i = 0; i < 4; i++) uy[i] = fmaf((float)(ybase + i), step, -1.0f);

    // Block-level skip: nearest tile point outside unit circle.
    {
        float nx = (ux_lo > 0.0f) ? ux_lo : ((ux_hi < 0.0f) ? ux_hi : 0.0f);
        float ny = (uy_lo > 0.0f) ? uy_lo : ((uy_hi < 0.0f) ? uy_hi : 0.0f);
        if (nx * nx + ny * ny > 1.0f) {
            #pragma unroll
            for (int i = 0; i < 4; i++) {
                size_t o = (size_t)(ybase + i) * HH + px;
                #pragma unroll
                for (int q = 0; q < 8; q++)
                    ob[(size_t)q * HH * HH + o] = 0.0f;
            }
            return;
        }
    }

    // Per-angle window metadata from tile-corner extremes (-1 floor guard),
    // with the angle's smem slot folded into the offset.
    if (tid < AA) {
        float cs = g_cs[tid];
        float ns = g_ns[tid];
        float mn = fminf(ux_lo * cs, ux_hi * cs)
                 + fminf(uy_lo * ns, uy_hi * ns) + 511.5f;
        float jminf = floorf(mn) - 1.0f;
        float off   = 511.5f - jminf + (float)((tid % CH) * WIN);
        s_meta[tid] = make_float4(cs, ns, off, 0.0f);
        s_jmin[tid] = (int)jminf;
    }

    // Warp early-out using NEAREST pixel of each lane's 4-row strip.
    float uy2min = (uy[0] * uy[3] <= 0.0f)
                 ? 0.0f
                 : fminf(uy[0] * uy[0], uy[3] * uy[3]);
    const bool active = !__all_sync(0xFFFFFFFFu, ux * ux + uy2min > 1.0f);

    float acc[8][4];
    #pragma unroll
    for (int q = 0; q < 8; q++)
        #pragma unroll
        for (int i = 0; i < 4; i++) acc[q][i] = 0.0f;

    const uint4* __restrict__ wq = g_wv + (size_t)bo * AA * ROWP;

    const unsigned int sw_base = (unsigned int)__cvta_generic_to_shared(&s_w[0][0]);

    // Stage one chunk's windows into buffer `buf` via cp.async (no commit).
    auto stage = [&](int ch, int buf) {
        const int abase = ch * CH;
        unsigned int sb = sw_base + (unsigned int)buf * (CWIN * 16);
        for (int idx = tid; idx < CWIN; idx += 256) {
            int slot = idx / WIN;
            int k    = idx - slot * WIN;
            int a    = abase + slot;
            int src  = s_jmin[a] + 1 + k;
            src = min(max(src, 0), 1025);
            cp_async16(sb + idx * 16, wq + (size_t)a * ROWP + src);
        }
    };

    __syncthreads();               // meta/jmin visible to all stagers
    stage(0, 0);
    cp_async_commit();

    for (int ch = 0; ch < NCH; ch++) {
        const int  buf   = ch & 1;
        const int  abase = ch * CH;

        cp_async_wait0();          // this chunk's data landed (this thread)
        __syncthreads();           // ...and everyone else's; prev compute done

        if (ch + 1 < NCH) {        // prefetch next chunk into other buffer
            stage(ch + 1, buf ^ 1);
            cp_async_commit();
        }

        if (active) {
            const uint4* __restrict__ wcur = s_w[buf];
            #pragma unroll 6
            for (int slot = 0; slot < CH; slot++) {
                float4 m = s_meta[abase + slot];
                float base = fmaf(ux, m.x, m.z);     // window coord incl. slot
                #pragma unroll
                for (int i = 0; i < 4; i++) {
                    float kf  = fmaf(uy[i], m.y, base);
                    int   k   = __float2int_rd(kf);          // k, k+1 in window
                    float fy  = kf - (float)k;
                    __half2 fy2 = __float2half2_rn(fy);
                    uint4 w0 = wcur[k];                      // v[j0]  8 batches
                    uint4 w1 = wcur[k + 1];                  // v[j0+1]
                    __half2 a01 = *reinterpret_cast<__half2*>(&w0.x);
                    __half2 a23 = *reinterpret_cast<__half2*>(&w0.y);
                    __half2 a45 = *reinterpret_cast<__half2*>(&w0.z);
                    __half2 a67 = *reinterpret_cast<__half2*>(&w0.w);
                    __half2 b01 = *reinterpret_cast<__half2*>(&w1.x);
                    __half2 b23 = *reinterpret_cast<__half2*>(&w1.y);
                    __half2 b45 = *reinterpret_cast<__half2*>(&w1.z);
                    __half2 b67 = *reinterpret_cast<__half2*>(&w1.w);
                    __half2 r01 = __hfma2(fy2, __hsub2(b01, a01), a01);
                    __half2 r23 = __hfma2(fy2, __hsub2(b23, a23), a23);
                    __half2 r45 = __hfma2(fy2, __hsub2(b45, a45), a45);
                    __half2 r67 = __hfma2(fy2, __hsub2(b67, a67), a67);
                    acc[0][i] += __low2float(r01);
                    acc[1][i] += __high2float(r01);
                    acc[2][i] += __low2float(r23);
                    acc[3][i] += __high2float(r23);
                    acc[4][i] += __low2float(r45);
                    acc[5][i] += __high2float(r45);
                    acc[6][i] += __low2float(r67);
                    acc[7][i] += __high2float(r67);
                }
            }
        }
    }

    const float scale = (float)(3.14159265358979323846 / 360.0);  // pi / (2*A)
    #pragma unroll
    for (int i = 0; i < 4; i++) {
        float r2 = fmaf(uy[i], uy[i], ux * ux);
        bool  in = (r2 <= 1.0f);
        size_t o = (size_t)(ybase + i) * HH + px;
        #pragma unroll
        for (int q = 0; q < 8; q++)
            ob[(size_t)q * HH * HH + o] = in ? acc[q][i] * scale : 0.0f;
    }
}

// ---------------------------------------------------------------------------
extern "C" void kernel_launch(void* const* d_in, const int* in_sizes, int n_in,
                              void* d_out, int out_size) {
    const float* x = (const float*)d_in[0];
    float* out = (float*)d_out;

    transpose_kernel<<<dim3(6, HH / 32, BB), dim3(32, 8)>>>(x);
    filter_kernel<<<dim3(AA, NBQ), 256>>>();
    backproject_kernel<<<dim3(HH / 32, HH / 32, NBO), dim3(32, 8)>>>(out);
}

// round 15
// speedup vs baseline: 1.1557x; 1.1557x over previous
#include <cuda_runtime.h>
#include <cuda_fp16.h>
#include <cstdint>
#include <math.h>

#define HH 1024      // detector size / image size
#define AA 180       // number of angles
#define BB 16        // batch
#define NBQ (BB / 4) // batch quads
#define NBO (BB / 8) // batch octets

#define ROWP 1028    // uint4 entries per padded row (valid src 0..1025)
#define MTAP 64      // filter taps: m < MTAP, i.e. |d| <= 127 (tail ~1.3e-4 rel)

// Interleaved fp16 window entries, one uint4 = [v01, d01, v23, d23] per
// detector position j, 4 batches per entry:
//   v01 = half2( v_b0[j-1], v_b1[j-1] ),  d01 = half2( dv_b0[j], dv_b1[j] )
//   v23/d23 same for batches 2,3;  dv[j] = v[j]-v[j-1];  v[-1]=v[1024]=0.
// Bilinear pair (v[j0], v[j0+1]) lives at j = j0+1.
__device__ uint4 g_w4[NBQ * AA * ROWP];
// Transposed raw sinogram: g_xt[b][a][h] (for coalesced filter input reads)
__device__ float g_xt[BB * AA * HH];
// Pre-scaled trig: g_cs[a] = 512*cos(theta_a), g_ns[a] = -512*sin(theta_a)
__device__ float g_cs[AA];
__device__ float g_ns[AA];

// ---------------------------------------------------------------------------
// cp.async helpers (16-byte, L2-cg path)
// ---------------------------------------------------------------------------
__device__ __forceinline__ void cp_async16(unsigned int dst_smem, const void* src) {
    asm volatile("cp.async.cg.shared.global [%0], [%1], 16;\n"
                 :: "r"(dst_smem), "l"(src));
}
__device__ __forceinline__ void cp_async_commit() {
    asm volatile("cp.async.commit_group;\n");
}
__device__ __forceinline__ void cp_async_wait0() {
    asm volatile("cp.async.wait_group 0;\n" ::: "memory");
}

// ---------------------------------------------------------------------------
// Kernel 0: coalesced transpose x[b][h][a] -> g_xt[b][a][h].
// Block 32x8, 32x32 tile, 4 elements per thread (ILP for latency hiding).
// ---------------------------------------------------------------------------
__global__ __launch_bounds__(256) void transpose_kernel(const float* __restrict__ x) {
    __shared__ float t[32][33];
    const int b  = blockIdx.z;
    const int a0 = blockIdx.x * 32;
    const int h0 = blockIdx.y * 32;

    const int a = a0 + threadIdx.x;
    #pragma unroll
    for (int j = 0; j < 4; j++) {
        int h = h0 + threadIdx.y + 8 * j;
        t[threadIdx.y + 8 * j][threadIdx.x] =
            (a < AA) ? x[((size_t)b * HH + h) * AA + a] : 0.0f;
    }
    __syncthreads();

    const int ho = h0 + threadIdx.x;
    #pragma unroll
    for (int j = 0; j < 4; j++) {
        int ao = a0 + threadIdx.y + 8 * j;
        if (ao < AA)
            g_xt[((size_t)b * AA + ao) * HH + ho] = t[threadIdx.x][threadIdx.y + 8 * j];
    }
}

// ---------------------------------------------------------------------------
// Kernel 1: angle-resample + truncated ramp-filter convolution (equivalent to
// the reference's wrap-free padded-FFT filtering; taps beyond |d|=127 dropped,
// tail ~1.3e-4 relative, under the fp16 window quantization).
// 4 batches (one quad) per block -> assembles COMPLETE uint4 entries and
// stores them with coalesced STG.128.
// One block per (angle, quad). 256 threads, 4 outputs per thread per batch.
// ---------------------------------------------------------------------------
#define FPAD 128                 // conv pad each side (>= MTAP*2-1)
#define FROW (FPAD + HH + FPAD)  // 1280 floats per padded column

__global__ __launch_bounds__(256) void filter_kernel() {
    const int a   = blockIdx.x;
    const int bq  = blockIdx.y;       // batch quad
    const int tid = threadIdx.x;

    if (bq == 0 && tid == 0) {
        float tf = (float)a * 0.017453292519943295f;   // reference f32 angle
        double t = (double)tf;
        g_cs[a] = (float)cos(t) * 512.0f;
        g_ns[a] = (float)(-sin(t)) * 512.0f;
    }

    __shared__ float sin_[4][FROW];   // padded resampled columns (zeros outside)
    __shared__ float vcol[4][HH];     // filtered columns
    __shared__ float coef[MTAP];      // coef[m] = -2 / (pi*(2m+1))^2

    #pragma unroll
    for (int q = 0; q < 4; q++) {
        for (int i = tid; i < FPAD; i += 256) {
            sin_[q][i] = 0.0f;
            sin_[q][FPAD + HH + i] = 0.0f;
        }
    }
    if (tid < MTAP) {
        float d  = 2.0f * (float)tid + 1.0f;
        float pd = 3.14159265358979323846f * d;
        coef[tid] = -2.0f / (pd * pd);
    }

    // angle interpolation weights (commute with the linear filter)
    float ix = (float)a * (float)(180.0 / 179.0) - 0.5f;
    float fl = floorf(ix);
    int   i0 = (int)fl;
    float fx = ix - fl;
    int   i1 = i0 + 1;
    float w0 = (i0 >= 0 && i0 < AA) ? (1.0f - fx) : 0.0f;
    float w1 = (i1 >= 0 && i1 < AA) ? fx : 0.0f;
    int   c0 = min(max(i0, 0), AA - 1);
    int   c1 = min(max(i1, 0), AA - 1);

    // coalesced loads of the 4 batches' resampled columns
    #pragma unroll
    for (int q = 0; q < 4; q++) {
        int b = 4 * bq + q;
        const float* __restrict__ r0 = g_xt + ((size_t)b * AA + c0) * HH;
        const float* __restrict__ r1 = g_xt + ((size_t)b * AA + c1) * HH;
        for (int k = tid; k < HH; k += 256) {
            sin_[q][FPAD + k] = w0 * r0[k] + w1 * r1[k];
        }
    }
    __syncthreads();

    // truncated ramp convolution, batch by batch (order matches prior rounds)
    #pragma unroll
    for (int q = 0; q < 4; q++) {
        const float* __restrict__ s = sin_[q];
        const int p0 = FPAD + tid;
        float acc0 = 0.5f * s[p0];
        float acc1 = 0.5f * s[p0 + 256];
        float acc2 = 0.5f * s[p0 + 512];
        float acc3 = 0.5f * s[p0 + 768];

        #pragma unroll 8
        for (int m = 0; m < MTAP; m++) {
            int   d = 2 * m + 1;
            float c = coef[m];
            acc0 = fmaf(c, s[p0 - d]       + s[p0 + d],       acc0);
            acc1 = fmaf(c, s[p0 + 256 - d] + s[p0 + 256 + d], acc1);
            acc2 = fmaf(c, s[p0 + 512 - d] + s[p0 + 512 + d], acc2);
            acc3 = fmaf(c, s[p0 + 768 - d] + s[p0 + 768 + d], acc3);
        }
        vcol[q][tid]       = acc0;
        vcol[q][tid + 256] = acc1;
        vcol[q][tid + 512] = acc2;
        vcol[q][tid + 768] = acc3;
    }
    __syncthreads();

    // assemble & store complete uint4 entries, coalesced STG.128
    uint4* __restrict__ wrow = g_w4 + ((size_t)bq * AA + a) * ROWP;
    for (int j = tid; j < 1026; j += 256) {
        float vm1[4], v0[4];
        #pragma unroll
        for (int q = 0; q < 4; q++) {
            vm1[q] = (j >= 1 && j <= 1024) ? vcol[q][j - 1] : 0.0f;   // v[j-1]
            v0[q]  = (j < 1024)            ? vcol[q][j]     : 0.0f;   // v[j]
        }
        __half2 v01 = __floats2half2_rn(vm1[0], vm1[1]);
        __half2 d01 = __floats2half2_rn(v0[0] - vm1[0], v0[1] - vm1[1]);
        __half2 v23 = __floats2half2_rn(vm1[2], vm1[3]);
        __half2 d23 = __floats2half2_rn(v0[2] - vm1[2], v0[3] - vm1[3]);
        uint4 e;
        e.x = *reinterpret_cast<unsigned int*>(&v01);
        e.y = *reinterpret_cast<unsigned int*>(&d01);
        e.z = *reinterpret_cast<unsigned int*>(&v23);
        e.w = *reinterpret_cast<unsigned int*>(&d23);
        wrow[j] = e;
    }
}

// ---------------------------------------------------------------------------
// Kernel 2: backprojection, 8 batches per block, fp16 interleaved (v,d)
// uint4 windows -> two disjoint-plane LDS.128 per 8 samples. Block = 32x8 =
// 256 threads = 32x32 pixel tile, 4 y-rows and 8 batches per thread.
// Double-buffered window staging via cp.async -- prefetch chunk c+1 while
// computing chunk c; ONE barrier per chunk, staging latency hidden.
// Window bounds from tile-corner extremes -> every in-tile sample maps to
// k in [0, WIN-2]; no per-sample clamp.
// ---------------------------------------------------------------------------
#define CH  12                 // angles per chunk (180 = 15 * 12)
#define NCH (AA / CH)
#define WIN 48                 // window entries per angle (44 span + guards)
#define CWIN (CH * WIN)        // 576 entries per plane per chunk

__global__ __launch_bounds__(256) void backproject_kernel(float* __restrict__ out) {
    __shared__ float4 s_meta[AA];            // cs, ns, off(=511.5-jminf+slot*WIN), 0
    __shared__ int    s_jmin[AA];
    __shared__ uint4  s_w[2][2 * CWIN];      // [buf][plane0: b0-3 | plane1: b4-7]

    const int tid = threadIdx.y * 32 + threadIdx.x;
    const int bo  = blockIdx.z;              // batch octet
    const int x0  = blockIdx.x * 32;
    const int y0  = blockIdx.y * 32;

    const float step = 2.0f / 1023.0f;
    const float ux_lo = fmaf((float)x0,        step, -1.0f);
    const float ux_hi = fmaf((float)(x0 + 31), step, -1.0f);
    const float uy_lo = fmaf((float)y0,        step, -1.0f);
    const float uy_hi = fmaf((float)(y0 + 31), step, -1.0f);

    const int px    = x0 + threadIdx.x;
    const int ybase = y0 + threadIdx.y * 4;
    float* ob = out + (size_t)(8 * bo) * HH * HH;

    const float ux = fmaf((float)px, step, -1.0f);
    float uy[4];
    #pragma unroll
    for (int i = 0; i < 4; i++) uy[i] = fmaf((float)(ybase + i), step, -1.0f);

    // Block-level skip: nearest tile point outside unit circle.
    {
        float nx = (ux_lo > 0.0f) ? ux_lo : ((ux_hi < 0.0f) ? ux_hi : 0.0f);
        float ny = (uy_lo > 0.0f) ? uy_lo : ((uy_hi < 0.0f) ? uy_hi : 0.0f);
        if (nx * nx + ny * ny > 1.0f) {
            #pragma unroll
            for (int i = 0; i < 4; i++) {
                size_t o = (size_t)(ybase + i) * HH + px;
                #pragma unroll
                for (int q = 0; q < 8; q++)
                    ob[(size_t)q * HH * HH + o] = 0.0f;
            }
            return;
        }
    }

    // Per-angle window metadata from tile-corner extremes (-1 floor guard),
    // with the angle's smem slot folded into the offset.
    if (tid < AA) {
        float cs = g_cs[tid];
        float ns = g_ns[tid];
        float mn = fminf(ux_lo * cs, ux_hi * cs)
                 + fminf(uy_lo * ns, uy_hi * ns) + 511.5f;
        float jminf = floorf(mn) - 1.0f;
        float off   = 511.5f - jminf + (float)((tid % CH) * WIN);
        s_meta[tid] = make_float4(cs, ns, off, 0.0f);
        s_jmin[tid] = (int)jminf;
    }

    // Warp early-out using NEAREST pixel of each lane's 4-row strip.
    float uy2min = (uy[0] * uy[3] <= 0.0f)
                 ? 0.0f
                 : fminf(uy[0] * uy[0], uy[3] * uy[3]);
    const bool active = !__all_sync(0xFFFFFFFFu, ux * ux + uy2min > 1.0f);

    float acc[8][4];
    #pragma unroll
    for (int q = 0; q < 8; q++)
        #pragma unroll
        for (int i = 0; i < 4; i++) acc[q][i] = 0.0f;

    const uint4* __restrict__ wqA = g_w4 + (size_t)(2 * bo)     * AA * ROWP;
    const uint4* __restrict__ wqB = g_w4 + (size_t)(2 * bo + 1) * AA * ROWP;

    const unsigned int sw_base = (unsigned int)__cvta_generic_to_shared(&s_w[0][0]);

    // Stage one chunk's windows into buffer `buf` via cp.async (no commit).
    // 576 entries / 256 threads = 2 full strides + 1 predicated.
    auto stage = [&](int ch, int buf) {
        const int abase = ch * CH;
        unsigned int sb = sw_base + (unsigned int)buf * (2 * CWIN * 16);
        #pragma unroll
        for (int st = 0; st < 3; st++) {
            int idx = tid + st * 256;
            if (st < 2 || idx < CWIN) {
                int slot = idx / WIN;
                int k    = idx - slot * WIN;
                int a    = abase + slot;
                int src  = s_jmin[a] + 1 + k;
                src = min(max(src, 0), 1025);
                size_t g = (size_t)a * ROWP + src;
                cp_async16(sb + idx * 16,          wqA + g);
                cp_async16(sb + (CWIN + idx) * 16, wqB + g);
            }
        }
    };

    __syncthreads();               // meta/jmin visible to all stagers
    stage(0, 0);
    cp_async_commit();

    for (int ch = 0; ch < NCH; ch++) {
        const int  buf   = ch & 1;
        const int  abase = ch * CH;

        cp_async_wait0();          // this chunk's data landed (this thread)
        __syncthreads();           // ...and everyone else's; prev compute done

        if (ch + 1 < NCH) {        // prefetch next chunk into other buffer
            stage(ch + 1, buf ^ 1);
            cp_async_commit();
        }

        if (active) {
            const uint4* __restrict__ wcur = s_w[buf];
            #pragma unroll 6
            for (int slot = 0; slot < CH; slot++) {
                float4 m = s_meta[abase + slot];
                float base = fmaf(ux, m.x, m.z);     // window coord incl. slot
                #pragma unroll
                for (int i = 0; i < 4; i++) {
                    float kf  = fmaf(uy[i], m.y, base);
                    int   k   = __float2int_rd(kf);          // in [0, CWIN)
                    float fy  = kf - (float)k;
                    __half2 fy2 = __float2half2_rn(fy);
                    uint4 wA = wcur[k];                      // LDS.128, b0-3
                    uint4 wB = wcur[k + CWIN];               // LDS.128, b4-7
                    __half2 rA0 = __hfma2(fy2, *reinterpret_cast<__half2*>(&wA.y),
                                               *reinterpret_cast<__half2*>(&wA.x));
                    __half2 rA1 = __hfma2(fy2, *reinterpret_cast<__half2*>(&wA.w),
                                               *reinterpret_cast<__half2*>(&wA.z));
                    __half2 rB0 = __hfma2(fy2, *reinterpret_cast<__half2*>(&wB.y),
                                               *reinterpret_cast<__half2*>(&wB.x));
                    __half2 rB1 = __hfma2(fy2, *reinterpret_cast<__half2*>(&wB.w),
                                               *reinterpret_cast<__half2*>(&wB.z));
                    acc[0][i] += __low2float(rA0);
                    acc[1][i] += __high2float(rA0);
                    acc[2][i] += __low2float(rA1);
                    acc[3][i] += __high2float(rA1);
                    acc[4][i] += __low2float(rB0);
                    acc[5][i] += __high2float(rB0);
                    acc[6][i] += __low2float(rB1);
                    acc[7][i] += __high2float(rB1);
                }
            }
        }
    }

    const float scale = (float)(3.14159265358979323846 / 360.0);  // pi / (2*A)
    #pragma unroll
    for (int i = 0; i < 4; i++) {
        float r2 = fmaf(uy[i], uy[i], ux * ux);
        bool  in = (r2 <= 1.0f);
        size_t o = (size_t)(ybase + i) * HH + px;
        #pragma unroll
        for (int q = 0; q < 8; q++)
            ob[(size_t)q * HH * HH + o] = in ? acc[q][i] * scale : 0.0f;
    }
}

// ---------------------------------------------------------------------------
extern "C" void kernel_launch(void* const* d_in, const int* in_sizes, int n_in,
                              void* d_out, int out_size) {
    const float* x = (const float*)d_in[0];
    float* out = (float*)d_out;

    transpose_kernel<<<dim3(6, HH / 32, BB), dim3(32, 8)>>>(x);
    filter_kernel<<<dim3(AA, NBQ), 256>>>();
    backproject_kernel<<<dim3(HH / 32, HH / 32, NBO), dim3(32, 8)>>>(out);
}

// round 16
// speedup vs baseline: 1.1939x; 1.0331x over previous
#include <cuda_runtime.h>
#include <cuda_fp16.h>
#include <cstdint>
#include <math.h>

#define HH 1024      // detector size / image size
#define AA 180       // number of angles
#define BB 16        // batch
#define NBQ (BB / 4) // batch quads
#define NBO (BB / 8) // batch octets

#define ROWP 1028    // uint4 entries per padded row (valid src 0..1025)
#define MTAP 64      // filter taps: m < MTAP, i.e. |d| <= 127 (tail ~1.3e-4 rel)

// Interleaved fp16 window entries, one uint4 = [v01, d01, v23, d23] per
// detector position j, 4 batches per entry:
//   v01 = half2( v_b0[j-1], v_b1[j-1] ),  d01 = half2( dv_b0[j], dv_b1[j] )
//   v23/d23 same for batches 2,3;  dv[j] = v[j]-v[j-1];  v[-1]=v[1024]=0.
// Bilinear pair (v[j0], v[j0+1]) lives at j = j0+1.
__device__ uint4 g_w4[NBQ * AA * ROWP];
// Transposed raw sinogram: g_xt[b][a][h] (for coalesced filter input reads)
__device__ float g_xt[BB * AA * HH];
// Pre-scaled trig: g_cs[a] = 512*cos(theta_a), g_ns[a] = -512*sin(theta_a)
__device__ float g_cs[AA];
__device__ float g_ns[AA];

// ---------------------------------------------------------------------------
// cp.async helpers (16-byte, L2-cg path)
// ---------------------------------------------------------------------------
__device__ __forceinline__ void cp_async16(unsigned int dst_smem, const void* src) {
    asm volatile("cp.async.cg.shared.global [%0], [%1], 16;\n"
                 :: "r"(dst_smem), "l"(src));
}
__device__ __forceinline__ void cp_async_commit() {
    asm volatile("cp.async.commit_group;\n");
}
__device__ __forceinline__ void cp_async_wait0() {
    asm volatile("cp.async.wait_group 0;\n" ::: "memory");
}

// ---------------------------------------------------------------------------
// Kernel 0: coalesced transpose x[b][h][a] -> g_xt[b][a][h].
// Block 32x8, 32x32 tile, 4 elements per thread (ILP for latency hiding).
// ---------------------------------------------------------------------------
__global__ __launch_bounds__(256) void transpose_kernel(const float* __restrict__ x) {
    __shared__ float t[32][33];
    const int b  = blockIdx.z;
    const int a0 = blockIdx.x * 32;
    const int h0 = blockIdx.y * 32;

    const int a = a0 + threadIdx.x;
    #pragma unroll
    for (int j = 0; j < 4; j++) {
        int h = h0 + threadIdx.y + 8 * j;
        t[threadIdx.y + 8 * j][threadIdx.x] =
            (a < AA) ? x[((size_t)b * HH + h) * AA + a] : 0.0f;
    }
    __syncthreads();

    const int ho = h0 + threadIdx.x;
    #pragma unroll
    for (int j = 0; j < 4; j++) {
        int ao = a0 + threadIdx.y + 8 * j;
        if (ao < AA)
            g_xt[((size_t)b * AA + ao) * HH + ho] = t[threadIdx.x][threadIdx.y + 8 * j];
    }
}

// ---------------------------------------------------------------------------
// Kernel 1: angle-resample + truncated ramp-filter convolution (equivalent to
// the reference's wrap-free padded-FFT filtering; taps beyond |d|=127 dropped,
// tail ~1.3e-4 relative, under the fp16 window quantization).
// 4 batches (one quad) per block -> assembles COMPLETE uint4 entries and
// stores them with coalesced STG.128.
// One block per (angle, quad). 256 threads, 4 outputs per thread per batch.
// ---------------------------------------------------------------------------
#define FPAD 128                 // conv pad each side (>= MTAP*2-1)
#define FROW (FPAD + HH + FPAD)  // 1280 floats per padded column

__global__ __launch_bounds__(256) void filter_kernel() {
    const int a   = blockIdx.x;
    const int bq  = blockIdx.y;       // batch quad
    const int tid = threadIdx.x;

    if (bq == 0 && tid == 0) {
        float tf = (float)a * 0.017453292519943295f;   // reference f32 angle
        double t = (double)tf;
        g_cs[a] = (float)cos(t) * 512.0f;
        g_ns[a] = (float)(-sin(t)) * 512.0f;
    }

    __shared__ float sin_[4][FROW];   // padded resampled columns (zeros outside)
    __shared__ float vcol[4][HH];     // filtered columns
    __shared__ float coef[MTAP];      // coef[m] = -2 / (pi*(2m+1))^2

    #pragma unroll
    for (int q = 0; q < 4; q++) {
        for (int i = tid; i < FPAD; i += 256) {
            sin_[q][i] = 0.0f;
            sin_[q][FPAD + HH + i] = 0.0f;
        }
    }
    if (tid < MTAP) {
        float d  = 2.0f * (float)tid + 1.0f;
        float pd = 3.14159265358979323846f * d;
        coef[tid] = -2.0f / (pd * pd);
    }

    // angle interpolation weights (commute with the linear filter)
    float ix = (float)a * (float)(180.0 / 179.0) - 0.5f;
    float fl = floorf(ix);
    int   i0 = (int)fl;
    float fx = ix - fl;
    int   i1 = i0 + 1;
    float w0 = (i0 >= 0 && i0 < AA) ? (1.0f - fx) : 0.0f;
    float w1 = (i1 >= 0 && i1 < AA) ? fx : 0.0f;
    int   c0 = min(max(i0, 0), AA - 1);
    int   c1 = min(max(i1, 0), AA - 1);

    // coalesced loads of the 4 batches' resampled columns
    #pragma unroll
    for (int q = 0; q < 4; q++) {
        int b = 4 * bq + q;
        const float* __restrict__ r0 = g_xt + ((size_t)b * AA + c0) * HH;
        const float* __restrict__ r1 = g_xt + ((size_t)b * AA + c1) * HH;
        for (int k = tid; k < HH; k += 256) {
            sin_[q][FPAD + k] = w0 * r0[k] + w1 * r1[k];
        }
    }
    __syncthreads();

    // truncated ramp convolution, batch by batch (order matches prior rounds)
    #pragma unroll
    for (int q = 0; q < 4; q++) {
        const float* __restrict__ s = sin_[q];
        const int p0 = FPAD + tid;
        float acc0 = 0.5f * s[p0];
        float acc1 = 0.5f * s[p0 + 256];
        float acc2 = 0.5f * s[p0 + 512];
        float acc3 = 0.5f * s[p0 + 768];

        #pragma unroll 8
        for (int m = 0; m < MTAP; m++) {
            int   d = 2 * m + 1;
            float c = coef[m];
            acc0 = fmaf(c, s[p0 - d]       + s[p0 + d],       acc0);
            acc1 = fmaf(c, s[p0 + 256 - d] + s[p0 + 256 + d], acc1);
            acc2 = fmaf(c, s[p0 + 512 - d] + s[p0 + 512 + d], acc2);
            acc3 = fmaf(c, s[p0 + 768 - d] + s[p0 + 768 + d], acc3);
        }
        vcol[q][tid]       = acc0;
        vcol[q][tid + 256] = acc1;
        vcol[q][tid + 512] = acc2;
        vcol[q][tid + 768] = acc3;
    }
    __syncthreads();

    // assemble & store complete uint4 entries, coalesced STG.128
    uint4* __restrict__ wrow = g_w4 + ((size_t)bq * AA + a) * ROWP;
    for (int j = tid; j < 1026; j += 256) {
        float vm1[4], v0[4];
        #pragma unroll
        for (int q = 0; q < 4; q++) {
            vm1[q] = (j >= 1 && j <= 1024) ? vcol[q][j - 1] : 0.0f;   // v[j-1]
            v0[q]  = (j < 1024)            ? vcol[q][j]     : 0.0f;   // v[j]
        }
        __half2 v01 = __floats2half2_rn(vm1[0], vm1[1]);
        __half2 d01 = __floats2half2_rn(v0[0] - vm1[0], v0[1] - vm1[1]);
        __half2 v23 = __floats2half2_rn(vm1[2], vm1[3]);
        __half2 d23 = __floats2half2_rn(v0[2] - vm1[2], v0[3] - vm1[3]);
        uint4 e;
        e.x = *reinterpret_cast<unsigned int*>(&v01);
        e.y = *reinterpret_cast<unsigned int*>(&d01);
        e.z = *reinterpret_cast<unsigned int*>(&v23);
        e.w = *reinterpret_cast<unsigned int*>(&d23);
        wrow[j] = e;
    }
}

// ---------------------------------------------------------------------------
// Kernel 2: backprojection, 8 batches per block, fp16 interleaved (v,d)
// uint4 windows -> two disjoint-plane LDS.128 per 8 samples. Block = 32x8 =
// 256 threads = 32x32 pixel tile, 4 y-rows and 8 batches per thread.
// Double-buffered window staging via cp.async -- prefetch chunk c+1 while
// computing chunk c; ONE barrier per chunk, staging latency hidden.
// Window bounds from tile-corner extremes -> every in-tile sample maps to
// k in [0, WIN-2]; no per-sample clamp.
// ---------------------------------------------------------------------------
#define CH  12                 // angles per chunk (180 = 15 * 12)
#define NCH (AA / CH)
#define WIN 48                 // window entries per angle (44 span + guards)
#define CWIN (CH * WIN)        // 576 entries per plane per chunk

__global__ __launch_bounds__(256) void backproject_kernel(float* __restrict__ out) {
    __shared__ float4 s_meta[AA];            // cs, ns, off(=511.5-jminf+slot*WIN), 0
    __shared__ int    s_jmin[AA];
    __shared__ uint4  s_w[2][2 * CWIN];      // [buf][plane0: b0-3 | plane1: b4-7]

    const int tid = threadIdx.y * 32 + threadIdx.x;
    const int bo  = blockIdx.z;              // batch octet
    const int x0  = blockIdx.x * 32;
    const int y0  = blockIdx.y * 32;

    const float step = 2.0f / 1023.0f;
    const float ux_lo = fmaf((float)x0,        step, -1.0f);
    const float ux_hi = fmaf((float)(x0 + 31), step, -1.0f);
    const float uy_lo = fmaf((float)y0,        step, -1.0f);
    const float uy_hi = fmaf((float)(y0 + 31), step, -1.0f);

    const int px    = x0 + threadIdx.x;
    const int ybase = y0 + threadIdx.y * 4;
    float* ob = out + (size_t)(8 * bo) * HH * HH;

    const float ux = fmaf((float)px, step, -1.0f);
    float uy[4];
    #pragma unroll
    for (int i = 0; i < 4; i++) uy[i] = fmaf((float)(ybase + i), step, -1.0f);

    // Block-level skip: nearest tile point outside unit circle.
    {
        float nx = (ux_lo > 0.0f) ? ux_lo : ((ux_hi < 0.0f) ? ux_hi : 0.0f);
        float ny = (uy_lo > 0.0f) ? uy_lo : ((uy_hi < 0.0f) ? uy_hi : 0.0f);
        if (nx * nx + ny * ny > 1.0f) {
            #pragma unroll
            for (int i = 0; i < 4; i++) {
                size_t o = (size_t)(ybase + i) * HH + px;
                #pragma unroll
                for (int q = 0; q < 8; q++)
                    ob[(size_t)q * HH * HH + o] = 0.0f;
            }
            return;
        }
    }

    // Per-angle window metadata from tile-corner extremes (-1 floor guard),
    // with the angle's smem slot folded into the offset.
    if (tid < AA) {
        float cs = g_cs[tid];
        float ns = g_ns[tid];
        float mn = fminf(ux_lo * cs, ux_hi * cs)
                 + fminf(uy_lo * ns, uy_hi * ns) + 511.5f;
        float jminf = floorf(mn) - 1.0f;
        float off   = 511.5f - jminf + (float)((tid % CH) * WIN);
        s_meta[tid] = make_float4(cs, ns, off, 0.0f);
        s_jmin[tid] = (int)jminf;
    }

    // Warp early-out using NEAREST pixel of each lane's 4-row strip.
    float uy2min = (uy[0] * uy[3] <= 0.0f)
                 ? 0.0f
                 : fminf(uy[0] * uy[0], uy[3] * uy[3]);
    const bool active = !__all_sync(0xFFFFFFFFu, ux * ux + uy2min > 1.0f);

    float acc[8][4];
    #pragma unroll
    for (int q = 0; q < 8; q++)
        #pragma unroll
        for (int i = 0; i < 4; i++) acc[q][i] = 0.0f;

    const uint4* __restrict__ wqA = g_w4 + (size_t)(2 * bo)     * AA * ROWP;
    const uint4* __restrict__ wqB = g_w4 + (size_t)(2 * bo + 1) * AA * ROWP;

    const unsigned int sw_base = (unsigned int)__cvta_generic_to_shared(&s_w[0][0]);

    // Stage one chunk's windows into buffer `buf` via cp.async (no commit).
    auto stage = [&](int ch, int buf) {
        const int abase = ch * CH;
        unsigned int sb = sw_base + (unsigned int)buf * (2 * CWIN * 16);
        for (int idx = tid; idx < CWIN; idx += 256) {
            int slot = idx / WIN;
            int k    = idx - slot * WIN;
            int a    = abase + slot;
            int src  = s_jmin[a] + 1 + k;
            src = min(max(src, 0), 1025);
            size_t g = (size_t)a * ROWP + src;
            cp_async16(sb + idx * 16,          wqA + g);
            cp_async16(sb + (CWIN + idx) * 16, wqB + g);
        }
    };

    __syncthreads();               // meta/jmin visible to all stagers
    stage(0, 0);
    cp_async_commit();

    for (int ch = 0; ch < NCH; ch++) {
        const int  buf   = ch & 1;
        const int  abase = ch * CH;

        cp_async_wait0();          // this chunk's data landed (this thread)
        __syncthreads();           // ...and everyone else's; prev compute done

        if (ch + 1 < NCH) {        // prefetch next chunk into other buffer
            stage(ch + 1, buf ^ 1);
            cp_async_commit();
        }

        if (active) {
            const uint4* __restrict__ wcur = s_w[buf];
            #pragma unroll 6
            for (int slot = 0; slot < CH; slot++) {
                float4 m = s_meta[abase + slot];
                float base = fmaf(ux, m.x, m.z);     // window coord incl. slot
                #pragma unroll
                for (int i = 0; i < 4; i++) {
                    float kf  = fmaf(uy[i], m.y, base);
                    int   k   = __float2int_rd(kf);          // in [0, CWIN)
                    float fy  = kf - (float)k;
                    __half2 fy2 = __float2half2_rn(fy);
                    uint4 wA = wcur[k];                      // LDS.128, b0-3
                    uint4 wB = wcur[k + CWIN];               // LDS.128, b4-7
                    __half2 rA0 = __hfma2(fy2, *reinterpret_cast<__half2*>(&wA.y),
                                               *reinterpret_cast<__half2*>(&wA.x));
                    __half2 rA1 = __hfma2(fy2, *reinterpret_cast<__half2*>(&wA.w),
                                               *reinterpret_cast<__half2*>(&wA.z));
                    __half2 rB0 = __hfma2(fy2, *reinterpret_cast<__half2*>(&wB.y),
                                               *reinterpret_cast<__half2*>(&wB.x));
                    __half2 rB1 = __hfma2(fy2, *reinterpret_cast<__half2*>(&wB.w),
                                               *reinterpret_cast<__half2*>(&wB.z));
                    acc[0][i] += __low2float(rA0);
                    acc[1][i] += __high2float(rA0);
                    acc[2][i] += __low2float(rA1);
                    acc[3][i] += __high2float(rA1);
                    acc[4][i] += __low2float(rB0);
                    acc[5][i] += __high2float(rB0);
                    acc[6][i] += __low2float(rB1);
                    acc[7][i] += __high2float(rB1);
                }
            }
        }
    }

    const float scale = (float)(3.14159265358979323846 / 360.0);  // pi / (2*A)
    #pragma unroll
    for (int i = 0; i < 4; i++) {
        float r2 = fmaf(uy[i], uy[i], ux * ux);
        bool  in = (r2 <= 1.0f);
        size_t o = (size_t)(ybase + i) * HH + px;
        #pragma unroll
        for (int q = 0; q < 8; q++)
            ob[(size_t)q * HH * HH + o] = in ? acc[q][i] * scale : 0.0f;
    }
}

// ---------------------------------------------------------------------------
extern "C" void kernel_launch(void* const* d_in, const int* in_sizes, int n_in,
                              void* d_out, int out_size) {
    const float* x = (const float*)d_in[0];
    float* out = (float*)d_out;

    transpose_kernel<<<dim3(6, HH / 32, BB), dim3(32, 8)>>>(x);
    filter_kernel<<<dim3(AA, NBQ), 256>>>();
    backproject_kernel<<<dim3(HH / 32, HH / 32, NBO), dim3(32, 8)>>>(out);
}